// round 4
// baseline (speedup 1.0000x reference)
#include <cuda_runtime.h>
#include <math.h>

#define BB 4
#define CIN 64
#define COUT 64
#define HH 128
#define WW 128
#define KK 9
#define HW (HH*WW)

#define FMA2(d, a, b, c) asm("fma.rn.f32x2 %0, %1, %2, %3;" : "=l"(d) : "l"(a), "l"(b), "l"(c))
#define PACK2(d, lo, hi) asm("mov.b64 %0, {%1, %2};" : "=l"(d) : "f"(lo), "f"(hi))
#define UNPACK2(lo, hi, d) asm("mov.b64 {%0, %1}, %2;" : "=f"(lo), "=f"(hi) : "l"(d))

// ------------- device scratch (static, no allocation) -------------
__device__ float g_off[BB*10*HW];        // conv1 output, channels 0..9
__device__ float g_stats1[BB*5*2];       // GN1 sum/sumsq for groups 0..4
__device__ float g_xT[BB*HW*CIN];        // x transposed to [b][h][w][ci]
__device__ float g_wT[KK*CIN*COUT];      // w_dsc transposed to [k][ci][co]
__device__ float g_outraw[BB*COUT*HW];   // conv2 output before GN2
__device__ float g_stats2[BB*16*2];      // GN2 sum/sumsq

// ------------- prep: zero stats, transpose w_dsc -------------
__global__ void prep_kernel(const float* __restrict__ w_dsc) {
    int idx = blockIdx.x*256 + threadIdx.x;
    if (idx < KK*CIN*COUT) {
        int k  = idx / (CIN*COUT);
        int r  = idx % (CIN*COUT);
        int ci = r / COUT;
        int co = r % COUT;
        g_wT[idx] = w_dsc[(co*CIN + ci)*KK + k];
    }
    if (idx < BB*5*2)  g_stats1[idx] = 0.f;
    if (idx < BB*16*2) g_stats2[idx] = 0.f;
}

// ------------- conv1: 3x3 SAME, channels 0..9, f32x2 over channel pairs ----
// block (32,4)=128 threads; each thread: 2 w-pixels x 10 channels.
// grid (2, 32, 4)
__global__ __launch_bounds__(128) void conv1_kernel(
        const float* __restrict__ x,
        const float* __restrict__ w_off,
        const float* __restrict__ b_off) {
    __shared__ float sw2[576*12];    // [(ci*9+tap)][c] padded rows of 12
    __shared__ float s_sum[5], s_sq[5];
    int tid = threadIdx.y*32 + threadIdx.x;
    for (int i = tid; i < 5760; i += 128) {
        int c = i / 576;
        int r = i % 576;          // ci*9 + tap
        sw2[r*12 + c] = w_off[i];
    }
    if (tid < 5) { s_sum[tid] = 0.f; s_sq[tid] = 0.f; }
    __syncthreads();

    int b  = blockIdx.z;
    int h  = blockIdx.y*4 + threadIdx.y;
    int w0 = blockIdx.x*64 + threadIdx.x*2;

    unsigned long long acc2[5][2];
    #pragma unroll
    for (int c2 = 0; c2 < 5; c2++) {
        unsigned long long bp;
        PACK2(bp, b_off[c2*2], b_off[c2*2+1]);
        acc2[c2][0] = bp; acc2[c2][1] = bp;
    }

    const float* xb = x + (size_t)b*CIN*HW;
    for (int ci = 0; ci < CIN; ci++) {
        const float* xc = xb + ci*HW;
        #pragma unroll
        for (int dy = -1; dy <= 1; dy++) {
            int hy = h + dy;
            bool rv = (hy >= 0) && (hy < HH);
            float xv[4];
            #pragma unroll
            for (int j = 0; j < 4; j++) {
                int wx = w0 - 1 + j;
                xv[j] = (rv && wx >= 0 && wx < WW) ? xc[hy*WW + wx] : 0.f;
            }
            unsigned long long xd[4];
            #pragma unroll
            for (int j = 0; j < 4; j++) PACK2(xd[j], xv[j], xv[j]);
            #pragma unroll
            for (int tap = 0; tap < 3; tap++) {
                const float* wrow = &sw2[(ci*9 + (dy+1)*3 + tap)*12];
                const ulonglong2 wa = *(const ulonglong2*)wrow;       // pairs 0,1
                const ulonglong2 wb = *(const ulonglong2*)(wrow+4);   // pairs 2,3
                const unsigned long long wc = *(const unsigned long long*)(wrow+8); // pair 4
                #pragma unroll
                for (int j = 0; j < 2; j++) {
                    FMA2(acc2[0][j], wa.x, xd[j+tap], acc2[0][j]);
                    FMA2(acc2[1][j], wa.y, xd[j+tap], acc2[1][j]);
                    FMA2(acc2[2][j], wb.x, xd[j+tap], acc2[2][j]);
                    FMA2(acc2[3][j], wb.y, xd[j+tap], acc2[3][j]);
                    FMA2(acc2[4][j], wc,   xd[j+tap], acc2[4][j]);
                }
            }
        }
    }

    float ps[5] = {0,0,0,0,0}, pq[5] = {0,0,0,0,0};
    #pragma unroll
    for (int c2 = 0; c2 < 5; c2++) {
        float v0a, v1a, v0b, v1b;
        UNPACK2(v0a, v1a, acc2[c2][0]);   // px0: ch 2c2, 2c2+1
        UNPACK2(v0b, v1b, acc2[c2][1]);   // px1
        // channel 2c2: pixels w0, w0+1
        float2 e0 = make_float2(v0a, v0b);
        float2 e1 = make_float2(v1a, v1b);
        *(float2*)&g_off[((b*10 + 2*c2    )*HH + h)*WW + w0] = e0;
        *(float2*)&g_off[((b*10 + 2*c2 + 1)*HH + h)*WW + w0] = e1;
        ps[c2] += v0a + v0b + v1a + v1b;
        pq[c2] += v0a*v0a + v0b*v0b + v1a*v1a + v1b*v1b;
    }
    #pragma unroll
    for (int g = 0; g < 5; g++) {
        atomicAdd(&s_sum[g], ps[g]);
        atomicAdd(&s_sq[g],  pq[g]);
    }
    __syncthreads();
    if (tid < 5) {
        atomicAdd(&g_stats1[(b*5+tid)*2+0], s_sum[tid]);
        atomicAdd(&g_stats1[(b*5+tid)*2+1], s_sq[tid]);
    }
}

// ------------- transpose x: [b][ci][s] -> [b][s][ci] -------------
__global__ __launch_bounds__(256) void transpose_kernel(const float* __restrict__ x) {
    __shared__ float tile[32][33];
    int b  = blockIdx.z;
    int s0 = blockIdx.x*32;
    int c0 = blockIdx.y*32;
    #pragma unroll
    for (int r = 0; r < 4; r++) {
        int ci = c0 + threadIdx.y + r*8;
        tile[threadIdx.y + r*8][threadIdx.x] =
            x[((size_t)b*CIN + ci)*HW + s0 + threadIdx.x];
    }
    __syncthreads();
    #pragma unroll
    for (int r = 0; r < 4; r++) {
        int s = s0 + threadIdx.y + r*8;
        g_xT[((size_t)b*HW + s)*CIN + c0 + threadIdx.x] = tile[threadIdx.x][threadIdx.y + r*8];
    }
}

// ------------- fused: GN1+tanh+cumsum -> sample -> f32x2 GEMM -> stats2 ----
// grid (64, 4): (h-pair, b); 256 threads; dynamic smem.
// Block tile: 64 co x 256 px (2 rows x 128 w). Thread tile: 4 co x 16 px.
#define SM_WK 0
#define SM_V  4096
#define SM_RED 20480
#define SM_FLOATS 20992   // 83968 bytes

__global__ __launch_bounds__(256, 2) void fused_kernel(
        const float* __restrict__ g_gn_off,
        const float* __restrict__ b_gn_off,
        const float* __restrict__ b_dsc) {
    extern __shared__ float smf[];

    int t  = threadIdx.x;
    int b  = blockIdx.y;
    int h0 = blockIdx.x*2;

    // --- setup: per-pixel offsets (pixel p == t; coords live in registers) ---
    int pr = t >> 7;           // row within pair
    int pw = t & 127;          // w
    int ph = h0 + pr;

    float tv[9];
    #pragma unroll
    for (int c = 0; c < 9; c++) {
        int g = c >> 1;
        float s = g_stats1[(b*5 + g)*2 + 0];
        float q = g_stats1[(b*5 + g)*2 + 1];
        float mean = s * (1.f/32768.f);
        float var  = q * (1.f/32768.f) - mean*mean;
        float inv  = rsqrtf(var + 1e-5f);
        float v = g_off[((b*10 + c)*HH + ph)*WW + pw];
        tv[c] = tanhf((v - mean)*inv*g_gn_off[c] + b_gn_off[c]);
    }
    float yoff[9];
    yoff[4] = 0.f;
    yoff[3] = tv[3];
    yoff[2] = yoff[3] + tv[2];
    yoff[1] = yoff[2] + tv[1];
    yoff[0] = yoff[1] + tv[0];
    yoff[5] = tv[5];
    yoff[6] = yoff[5] + tv[6];
    yoff[7] = yoff[6] + tv[7];
    yoff[8] = yoff[7] + tv[8];

    int   ry0[9];
    float rwy[9];
    #pragma unroll
    for (int k = 0; k < 9; k++) {
        float yc = (float)ph + yoff[k];
        yc = fminf(fmaxf(yc, 0.f), 127.f);
        int y0 = (int)floorf(yc);
        y0 = min(max(y0, 0), 127);
        ry0[k] = y0;
        rwy[k] = yc - (float)y0;
    }

    int co0 = (t & 15) * 4;    // GEMM: 4 output channels
    int p0  = (t >> 4) * 16;   // GEMM: 16 pixels (8 f32x2 pairs)

    unsigned long long acc[4][8];
    #pragma unroll
    for (int i = 0; i < 4; i++)
        #pragma unroll
        for (int j = 0; j < 8; j++) acc[i][j] = 0ULL;

    const float* xTb = g_xT + (size_t)b*HW*CIN;

    for (int k = 0; k < 9; k++) {
        if (k) __syncthreads();
        // load weight slice [ci][co] (coalesced float4)
        {
            const float4* src = (const float4*)(g_wT + k*4096);
            float4* dst = (float4*)(smf + SM_WK);
            #pragma unroll
            for (int i = 0; i < 4; i++) dst[t + 256*i] = src[t + 256*i];
        }
        // build sampled tile v[ci][p] for pixel p == t (2-pt vertical lerp; wx==0)
        {
            int y0 = ry0[k];
            int y1 = min(y0+1, 127);
            float wy = rwy[k];
            int x0 = min(max(pw + k - 4, 0), 127);
            const float4* A = (const float4*)(xTb + (y0*WW + x0)*CIN);
            const float4* C = (const float4*)(xTb + (y1*WW + x0)*CIN);
            #pragma unroll
            for (int cc = 0; cc < 16; cc++) {
                float4 a = A[cc];
                float4 c = C[cc];
                smf[SM_V + (cc*4+0)*256 + t] = a.x + wy*(c.x - a.x);
                smf[SM_V + (cc*4+1)*256 + t] = a.y + wy*(c.y - a.y);
                smf[SM_V + (cc*4+2)*256 + t] = a.z + wy*(c.z - a.z);
                smf[SM_V + (cc*4+3)*256 + t] = a.w + wy*(c.w - a.w);
            }
        }
        __syncthreads();
        // GEMM: acc[c][j] += w[ci][co0+c] * v[ci][p0+2j..2j+1]
        #pragma unroll 4
        for (int ci = 0; ci < 64; ci++) {
            float4 w4 = *(const float4*)(smf + SM_WK + ci*64 + co0);
            unsigned long long wd0, wd1, wd2, wd3;
            PACK2(wd0, w4.x, w4.x);
            PACK2(wd1, w4.y, w4.y);
            PACK2(wd2, w4.z, w4.z);
            PACK2(wd3, w4.w, w4.w);
            const ulonglong2* vrow = (const ulonglong2*)(smf + SM_V + ci*256 + p0);
            ulonglong2 va = vrow[0];
            ulonglong2 vb = vrow[1];
            ulonglong2 vc = vrow[2];
            ulonglong2 vd = vrow[3];
            FMA2(acc[0][0], wd0, va.x, acc[0][0]);
            FMA2(acc[0][1], wd0, va.y, acc[0][1]);
            FMA2(acc[0][2], wd0, vb.x, acc[0][2]);
            FMA2(acc[0][3], wd0, vb.y, acc[0][3]);
            FMA2(acc[0][4], wd0, vc.x, acc[0][4]);
            FMA2(acc[0][5], wd0, vc.y, acc[0][5]);
            FMA2(acc[0][6], wd0, vd.x, acc[0][6]);
            FMA2(acc[0][7], wd0, vd.y, acc[0][7]);
            FMA2(acc[1][0], wd1, va.x, acc[1][0]);
            FMA2(acc[1][1], wd1, va.y, acc[1][1]);
            FMA2(acc[1][2], wd1, vb.x, acc[1][2]);
            FMA2(acc[1][3], wd1, vb.y, acc[1][3]);
            FMA2(acc[1][4], wd1, vc.x, acc[1][4]);
            FMA2(acc[1][5], wd1, vc.y, acc[1][5]);
            FMA2(acc[1][6], wd1, vd.x, acc[1][6]);
            FMA2(acc[1][7], wd1, vd.y, acc[1][7]);
            FMA2(acc[2][0], wd2, va.x, acc[2][0]);
            FMA2(acc[2][1], wd2, va.y, acc[2][1]);
            FMA2(acc[2][2], wd2, vb.x, acc[2][2]);
            FMA2(acc[2][3], wd2, vb.y, acc[2][3]);
            FMA2(acc[2][4], wd2, vc.x, acc[2][4]);
            FMA2(acc[2][5], wd2, vc.y, acc[2][5]);
            FMA2(acc[2][6], wd2, vd.x, acc[2][6]);
            FMA2(acc[2][7], wd2, vd.y, acc[2][7]);
            FMA2(acc[3][0], wd3, va.x, acc[3][0]);
            FMA2(acc[3][1], wd3, va.y, acc[3][1]);
            FMA2(acc[3][2], wd3, vb.x, acc[3][2]);
            FMA2(acc[3][3], wd3, vb.y, acc[3][3]);
            FMA2(acc[3][4], wd3, vc.x, acc[3][4]);
            FMA2(acc[3][5], wd3, vc.y, acc[3][5]);
            FMA2(acc[3][6], wd3, vd.x, acc[3][6]);
            FMA2(acc[3][7], wd3, vd.y, acc[3][7]);
        }
    }

    // epilogue: bias, write raw, reduce GN2 partial stats
    int orow = h0 + (p0 >> 7);
    int ow   = p0 & 127;
    float psum = 0.f, psq = 0.f;
    #pragma unroll
    for (int i = 0; i < 4; i++) {
        float bv = b_dsc[co0+i];
        float st[16];
        #pragma unroll
        for (int j = 0; j < 8; j++) {
            float lo, hi;
            UNPACK2(lo, hi, acc[i][j]);
            lo += bv; hi += bv;
            st[2*j] = lo; st[2*j+1] = hi;
            psum += lo + hi;
            psq  += lo*lo + hi*hi;
        }
        float* dst = &g_outraw[((b*COUT + co0+i)*HH + orow)*WW + ow];
        #pragma unroll
        for (int q = 0; q < 4; q++)
            *(float4*)(dst + q*4) = *(float4*)(st + q*4);
    }
    smf[SM_RED + t]       = psum;
    smf[SM_RED + 256 + t] = psq;
    __syncthreads();
    if (t < 16) {   // group g == t  (co0>>2 == t&15)
        float sm = 0.f, sq = 0.f;
        #pragma unroll
        for (int j = 0; j < 16; j++) {
            sm += smf[SM_RED + t + 16*j];
            sq += smf[SM_RED + 256 + t + 16*j];
        }
        atomicAdd(&g_stats2[(b*16 + t)*2 + 0], sm);
        atomicAdd(&g_stats2[(b*16 + t)*2 + 1], sq);
    }
}

// ------------- finalize: GN2 + ReLU (float4) -------------
__global__ void finalize_kernel(const float* __restrict__ g_gn,
                                const float* __restrict__ b_gn,
                                float* __restrict__ out) {
    int i4 = blockIdx.x*256 + threadIdx.x;   // 1048576 float4s
    int e  = i4 << 2;
    int b  = e >> 20;
    int co = (e >> 14) & 63;
    int g  = co >> 2;
    float s = g_stats2[(b*16+g)*2+0];
    float q = g_stats2[(b*16+g)*2+1];
    float mean = s * (1.f/65536.f);
    float var  = q * (1.f/65536.f) - mean*mean;
    float inv  = rsqrtf(var + 1e-5f);
    float ga = inv * g_gn[co];
    float be = b_gn[co] - mean*ga;
    float4 v = ((const float4*)g_outraw)[i4];
    v.x = fmaxf(v.x*ga + be, 0.f);
    v.y = fmaxf(v.y*ga + be, 0.f);
    v.z = fmaxf(v.z*ga + be, 0.f);
    v.w = fmaxf(v.w*ga + be, 0.f);
    ((float4*)out)[i4] = v;
}

// ------------- launch -------------
extern "C" void kernel_launch(void* const* d_in, const int* in_sizes, int n_in,
                              void* d_out, int out_size) {
    const float* x        = (const float*)d_in[0];
    const float* w_off    = (const float*)d_in[1];
    const float* b_off    = (const float*)d_in[2];
    const float* g_gn_off = (const float*)d_in[3];
    const float* b_gn_off = (const float*)d_in[4];
    const float* w_dsc    = (const float*)d_in[5];
    const float* b_dsc    = (const float*)d_in[6];
    const float* g_gn     = (const float*)d_in[7];
    const float* b_gn     = (const float*)d_in[8];
    float* out = (float*)d_out;

    cudaFuncSetAttribute(fused_kernel,
                         cudaFuncAttributeMaxDynamicSharedMemorySize,
                         SM_FLOATS*4);

    prep_kernel<<<144, 256>>>(w_dsc);
    conv1_kernel<<<dim3(2,32,4), dim3(32,4)>>>(x, w_off, b_off);
    transpose_kernel<<<dim3(512,2,4), dim3(32,8)>>>(x);
    fused_kernel<<<dim3(64,4), 256, SM_FLOATS*4>>>(g_gn_off, b_gn_off, b_dsc);
    finalize_kernel<<<4096, 256>>>(g_gn, b_gn, out);
}